// round 1
// baseline (speedup 1.0000x reference)
#include <cuda_runtime.h>

// Problem constants
#define B_ 128
#define T_ 100
#define I_ 1024
#define O_ 1024
#define EPSV 1e-8f

// Scratch (static __device__ arrays — allocation-free per harness rules)
__device__ float g_h[(size_t)B_ * T_ * O_];   // 52.4 MB: h = x@w, [B,T,O]
__device__ float g_d[(size_t)O_ * O_];        // 4 MB:  d = w^T w
__device__ float g_inv[O_];                   // 1/(norm+eps)
__device__ int   g_cnt[T_];                   // per-step spike counts

// ---------------------------------------------------------------------------
// GEMM 1: g_h[M,N] = x[M,K] * w[K,N], row-major, M=12800, N=K=1024.
// 128x128 block tile, 8x8 per-thread microtile, BK=8, 256 threads.
// ---------------------------------------------------------------------------
__global__ __launch_bounds__(256, 2) void gemm_h(
    const float* __restrict__ A, const float* __restrict__ Bm)
{
    __shared__ float As[8][128];
    __shared__ float Bs[8][132];   // +4 pad; row stride 528B (16B aligned)

    const int tid = threadIdx.x;
    const int bm = blockIdx.y * 128;
    const int bn = blockIdx.x * 128;
    const int K = I_, N = O_;

    const int arow = tid >> 1;            // 0..127
    const int acol = (tid & 1) * 4;       // 0 or 4
    const int brow = tid >> 5;            // 0..7
    const int bcol = (tid & 31) * 4;      // 0..124
    const int tr   = (tid >> 4) * 8;      // 0..120
    const int tc   = (tid & 15) * 8;      // 0..120

    float acc[8][8];
#pragma unroll
    for (int i = 0; i < 8; i++)
#pragma unroll
        for (int j = 0; j < 8; j++) acc[i][j] = 0.f;

    const float* Aptr = A + (size_t)(bm + arow) * K + acol;
    const float* Bptr = Bm + (size_t)brow * N + bn + bcol;

    for (int k0 = 0; k0 < K; k0 += 8) {
        float4 a4 = *(const float4*)(Aptr + k0);
        float4 b4 = *(const float4*)(Bptr + (size_t)k0 * N);
        __syncthreads();
        As[acol + 0][arow] = a4.x;
        As[acol + 1][arow] = a4.y;
        As[acol + 2][arow] = a4.z;
        As[acol + 3][arow] = a4.w;
        *(float4*)&Bs[brow][bcol] = b4;
        __syncthreads();
#pragma unroll
        for (int kk = 0; kk < 8; kk++) {
            float ar[8], br[8];
#pragma unroll
            for (int i = 0; i < 8; i++) ar[i] = As[kk][tr + i];
#pragma unroll
            for (int j = 0; j < 8; j++) br[j] = Bs[kk][tc + j];
#pragma unroll
            for (int i = 0; i < 8; i++)
#pragma unroll
                for (int j = 0; j < 8; j++) acc[i][j] += ar[i] * br[j];
        }
    }

#pragma unroll
    for (int i = 0; i < 8; i++)
#pragma unroll
        for (int j = 0; j < 8; j += 4) {
            float4 o4 = make_float4(acc[i][j], acc[i][j + 1], acc[i][j + 2], acc[i][j + 3]);
            *(float4*)&g_h[(size_t)(bm + tr + i) * N + bn + tc + j] = o4;
        }
}

// ---------------------------------------------------------------------------
// GEMM 2: g_d[i,o] = sum_a w[a,i]*w[a,o]  (A^T A, A = w [K=1024, 1024])
// ---------------------------------------------------------------------------
__global__ __launch_bounds__(256, 2) void gemm_d(const float* __restrict__ W)
{
    __shared__ float As[8][128];
    __shared__ float Bs[8][132];

    const int tid = threadIdx.x;
    const int bm = blockIdx.y * 128;
    const int bn = blockIdx.x * 128;
    const int K = I_, N = O_;

    const int brow = tid >> 5;
    const int bcol = (tid & 31) * 4;
    const int tr   = (tid >> 4) * 8;
    const int tc   = (tid & 15) * 8;

    float acc[8][8];
#pragma unroll
    for (int i = 0; i < 8; i++)
#pragma unroll
        for (int j = 0; j < 8; j++) acc[i][j] = 0.f;

    for (int k0 = 0; k0 < K; k0 += 8) {
        float4 a4 = *(const float4*)&W[(size_t)(k0 + brow) * N + bm + bcol];
        float4 b4 = *(const float4*)&W[(size_t)(k0 + brow) * N + bn + bcol];
        __syncthreads();
        *(float4*)&As[brow][bcol & 127] = a4;   // bcol < 128 always
        *(float4*)&Bs[brow][bcol] = b4;
        __syncthreads();
#pragma unroll
        for (int kk = 0; kk < 8; kk++) {
            float ar[8], br[8];
#pragma unroll
            for (int i = 0; i < 8; i++) ar[i] = As[kk][tr + i];
#pragma unroll
            for (int j = 0; j < 8; j++) br[j] = Bs[kk][tc + j];
#pragma unroll
            for (int i = 0; i < 8; i++)
#pragma unroll
                for (int j = 0; j < 8; j++) acc[i][j] += ar[i] * br[j];
        }
    }

#pragma unroll
    for (int i = 0; i < 8; i++)
#pragma unroll
        for (int j = 0; j < 8; j += 4) {
            float4 o4 = make_float4(acc[i][j], acc[i][j + 1], acc[i][j + 2], acc[i][j + 3]);
            *(float4*)&g_d[(size_t)(bm + tr + i) * N + bn + tc + j] = o4;
        }
}

// ---------------------------------------------------------------------------
// prep: inv_norm from diag(d), zero per-step counters
// ---------------------------------------------------------------------------
__global__ void prep_kernel()
{
    int idx = blockIdx.x * blockDim.x + threadIdx.x;
    if (idx < O_) g_inv[idx] = 1.0f / (g_d[(size_t)idx * O_ + idx] + EPSV);
    if (idx < T_) g_cnt[idx] = 0;
}

// ---------------------------------------------------------------------------
// Scan: one CTA per batch row. spk is {0,1} and ultra-sparse, so the two
// dense [1,O]x[O,O] products per step reduce to summing the active rows of
// d / v (exact: adding 0.0 terms cannot change an fp32 sum).
// ---------------------------------------------------------------------------
__global__ __launch_bounds__(256) void scan_kernel(
    const float* __restrict__ V,
    const float* __restrict__ bb,
    const float* __restrict__ beta_p,
    float* __restrict__ out)
{
    const int b   = blockIdx.x;
    const int tid = threadIdx.x;
    const float beta = beta_p[0];
    const float ombeta = 1.0f - beta;

    __shared__ float mem_s[O_];
    __shared__ float spk_s[O_];
    __shared__ int   act[O_];
    __shared__ int   nact;
    __shared__ int   scnt;

    for (int o = tid; o < O_; o += 256) { mem_s[o] = 0.f; spk_s[o] = 0.f; }
    if (tid == 0) { nact = 0; scnt = 0; }
    __syncthreads();

    const float* hrow = g_h + (size_t)b * T_ * O_;
    float*       orow = out + (size_t)b * T_ * O_;

    for (int t = 0; t < T_; t++) {
        // Invariant on entry: nact==0, scnt==0, spk_s = spikes of step t-1.
        // Phase 1: compact active indices.
        for (int o = tid; o < O_; o += 256) {
            if (spk_s[o] != 0.f) { int p = atomicAdd(&nact, 1); act[p] = o; }
        }
        __syncthreads();
        const int na = nact;

        // Phase 2: elementwise update (each thread owns 4 neurons).
        int cnt_local = 0;
        for (int o = tid; o < O_; o += 256) {
            float rst = 0.f, rec = 0.f;
            for (int a = 0; a < na; a++) {
                int i = act[a];
                rst += g_d[(size_t)i * O_ + o];
                rec += V[(size_t)i * O_ + o];
            }
            float m = (mem_s[o] - rst) * beta + (hrow[(size_t)t * O_ + o] + rec) * ombeta;
            mem_s[o] = m;
            float mthr = m * g_inv[o] - bb[o];
            float s = (mthr > 0.f) ? 1.0f : 0.0f;
            spk_s[o] = s;
            orow[(size_t)t * O_ + o] = s;
            cnt_local += (s != 0.f);
        }
        if (cnt_local) atomicAdd(&scnt, cnt_local);
        __syncthreads();
        if (tid == 0) {
            if (scnt) atomicAdd(&g_cnt[t], scnt);
            nact = 0; scnt = 0;
        }
        __syncthreads();
    }
}

// ---------------------------------------------------------------------------
// finalize: loss = 0.5*mean(spk^2) = 0.5*total/(B*T*O);
//           spread = max_t count_t / (B*O)
// ---------------------------------------------------------------------------
__global__ void finalize_kernel(float* __restrict__ out, int out_size)
{
    __shared__ int s_tot[128];
    __shared__ int s_max[128];
    const int tid = threadIdx.x;
    int tot = 0, mx = 0;
    for (int t = tid; t < T_; t += 128) {
        int c = g_cnt[t];
        tot += c;
        mx = (c > mx) ? c : mx;
    }
    s_tot[tid] = tot; s_max[tid] = mx;
    __syncthreads();
    for (int s = 64; s > 0; s >>= 1) {
        if (tid < s) {
            s_tot[tid] += s_tot[tid + s];
            s_max[tid] = (s_max[tid + s] > s_max[tid]) ? s_max[tid + s] : s_max[tid];
        }
        __syncthreads();
    }
    if (tid == 0) {
        const size_t base = (size_t)B_ * T_ * O_;
        if ((size_t)out_size >= base + 2) {
            out[base]     = 0.5f * (float)s_tot[0] / (float)((size_t)B_ * T_ * O_);
            out[base + 1] = (float)s_max[0] / (float)(B_ * O_);
        }
    }
}

// ---------------------------------------------------------------------------
extern "C" void kernel_launch(void* const* d_in, const int* in_sizes, int n_in,
                              void* d_out, int out_size)
{
    const float* x    = (const float*)d_in[0];   // [B,T,I]
    const float* w    = (const float*)d_in[1];   // [I,O]
    const float* v    = (const float*)d_in[2];   // [O,O]
    const float* beta = (const float*)d_in[3];   // [1]
    const float* bb   = (const float*)d_in[4];   // [O]
    // d_in[5] = sigma: unused in forward
    float* out = (float*)d_out;

    // 1) h = x @ w   (M=12800, N=1024, K=1024)
    gemm_h<<<dim3(O_ / 128, (B_ * T_) / 128), 256>>>(x, w);

    // 2) d = w^T w   (M=N=1024, K=1024)
    gemm_d<<<dim3(O_ / 128, O_ / 128), 256>>>(w);

    // 3) inv_norm + zero counters
    prep_kernel<<<4, 256>>>();

    // 4) per-batch recurrent scan
    scan_kernel<<<B_, 256>>>(v, bb, beta, out);

    // 5) scalar losses
    finalize_kernel<<<1, 128>>>(out, out_size);
}

// round 4
// speedup vs baseline: 1.3420x; 1.3420x over previous
#include <cuda_runtime.h>
#include <cstdint>

// Problem constants
#define B_ 128
#define T_ 100
#define I_ 1024
#define O_ 1024
#define EPSV 1e-8f

// Scratch (static __device__ arrays — allocation-free per harness rules)
__device__ float g_h[(size_t)B_ * T_ * O_];    // 52.4 MB: h = x@w, [B,T,O]
__device__ float g_d[(size_t)O_ * O_];         // 4 MB:  d = w^T w
__device__ float g_inv[O_];                    // 1/(norm+eps)
__device__ int   g_cnt[T_];                    // per-step spike counts

// ---------------------------------------------------------------------------
// helpers (plain sm_80-class PTX only — the harness targets sm_103 w/o 'a',
// so NO tcgen05/TMEM; tensor path is mma.sync tf32)
// ---------------------------------------------------------------------------
__device__ __forceinline__ float tf32r(float x) {
    uint32_t r;
    asm("cvt.rna.tf32.f32 %0, %1;" : "=r"(r) : "f"(x));
    return __uint_as_float(r);
}

__device__ __forceinline__ void mma_tf32(float c[4],
                                         float a0, float a1, float a2, float a3,
                                         float b0, float b1) {
    asm volatile(
        "mma.sync.aligned.m16n8k8.row.col.f32.tf32.tf32.f32 "
        "{%0,%1,%2,%3}, {%4,%5,%6,%7}, {%8,%9}, {%0,%1,%2,%3};"
        : "+f"(c[0]), "+f"(c[1]), "+f"(c[2]), "+f"(c[3])
        : "r"(__float_as_uint(a0)), "r"(__float_as_uint(a1)),
          "r"(__float_as_uint(a2)), "r"(__float_as_uint(a3)),
          "r"(__float_as_uint(b0)), "r"(__float_as_uint(b1)));
}

// ---------------------------------------------------------------------------
// gemm_h_mma: g_h[M,N] = x[M,K] * w[K,N], M=12800, N=K=1024.
// 3xTF32 (hi*hi + hi*lo + lo*hi) for near-fp32 accuracy on tensor pipes.
// CTA 128x128, 8 warps (2m x 4n, 64x32 each), BK=16, reg double buffer.
// smem layout per stage: Ah[16][133], Al[16][133], Bh[16][132], Bl[16][132]
//   A stored [k][m] (stride 133 kills the 8-row bank alias),
//   B stored [k][n] (stride 132 keeps float4 alignment).
// ---------------------------------------------------------------------------
#define ASTR 133
#define BSTR 132
#define OFF_AH 0
#define OFF_AL (16 * ASTR)
#define OFF_BH (2 * 16 * ASTR)
#define OFF_BL (2 * 16 * ASTR + 16 * BSTR)
#define STG    (2 * 16 * ASTR + 2 * 16 * BSTR)     // 8480 floats per stage
#define GH_SMEM_BYTES (2 * STG * 4)                // 67840 B

__global__ void __launch_bounds__(256) gemm_h_mma(
    const float* __restrict__ X, const float* __restrict__ W)
{
    extern __shared__ float sm[];
    const int tid  = threadIdx.x;
    const int wid  = tid >> 5;
    const int lane = tid & 31;
    const int g    = lane >> 2;     // group 0..7
    const int t4   = lane & 3;      // 0..3
    const int bm   = blockIdx.y * 128;
    const int bn   = blockIdx.x * 128;
    const int wm   = (wid >> 2) * 64;   // warp m offset in tile
    const int wn   = (wid & 3) * 32;    // warp n offset in tile

    // global-load assignments
    const int am = tid >> 1;            // A row 0..127
    const int ak = (tid & 1) * 8;       // A k sub-offset 0 or 8

    float acc[4][4][4];
#pragma unroll
    for (int i = 0; i < 4; i++)
#pragma unroll
        for (int j = 0; j < 4; j++)
#pragma unroll
            for (int q = 0; q < 4; q++) acc[i][j][q] = 0.f;

    float4 aR[2], bR[2];

    auto gload = [&](int k0) {
        const float* ap = X + (size_t)(bm + am) * I_ + k0 + ak;
        aR[0] = *(const float4*)(ap);
        aR[1] = *(const float4*)(ap + 4);
#pragma unroll
        for (int q = 0; q < 2; q++) {
            int idx = tid + q * 256;          // 0..511 float4s of 16x128 tile
            int r = idx >> 5, c = (idx & 31) * 4;
            bR[q] = *(const float4*)&W[(size_t)(k0 + r) * O_ + bn + c];
        }
    };

    auto sstore = [&](int s) {
        float* base = sm + s * STG;
#pragma unroll
        for (int q = 0; q < 2; q++) {
            float v[4] = {aR[q].x, aR[q].y, aR[q].z, aR[q].w};
#pragma unroll
            for (int j = 0; j < 4; j++) {
                float hi = tf32r(v[j]);
                float lo = tf32r(v[j] - hi);
                int k = ak + q * 4 + j;
                base[OFF_AH + k * ASTR + am] = hi;
                base[OFF_AL + k * ASTR + am] = lo;
            }
        }
#pragma unroll
        for (int q = 0; q < 2; q++) {
            int idx = tid + q * 256;
            int r = idx >> 5, c = (idx & 31) * 4;
            float v[4] = {bR[q].x, bR[q].y, bR[q].z, bR[q].w};
            float4 h4, l4;
            h4.x = tf32r(v[0]); l4.x = tf32r(v[0] - h4.x);
            h4.y = tf32r(v[1]); l4.y = tf32r(v[1] - h4.y);
            h4.z = tf32r(v[2]); l4.z = tf32r(v[2] - h4.z);
            h4.w = tf32r(v[3]); l4.w = tf32r(v[3] - h4.w);
            *(float4*)&base[OFF_BH + r * BSTR + c] = h4;
            *(float4*)&base[OFF_BL + r * BSTR + c] = l4;
        }
    };

    auto compute = [&](int s) {
        const float* base = sm + s * STG;
#pragma unroll
        for (int ks = 0; ks < 16; ks += 8) {
            const int r0 = ks + t4;
            const int r1 = ks + t4 + 4;
            float ah[4][4], al[4][4], bh[4][2], bl[4][2];
#pragma unroll
            for (int mt = 0; mt < 4; mt++) {
                const int col = wm + mt * 16 + g;
                ah[mt][0] = base[OFF_AH + r0 * ASTR + col];
                ah[mt][1] = base[OFF_AH + r0 * ASTR + col + 8];
                ah[mt][2] = base[OFF_AH + r1 * ASTR + col];
                ah[mt][3] = base[OFF_AH + r1 * ASTR + col + 8];
                al[mt][0] = base[OFF_AL + r0 * ASTR + col];
                al[mt][1] = base[OFF_AL + r0 * ASTR + col + 8];
                al[mt][2] = base[OFF_AL + r1 * ASTR + col];
                al[mt][3] = base[OFF_AL + r1 * ASTR + col + 8];
            }
#pragma unroll
            for (int nt = 0; nt < 4; nt++) {
                const int cn = wn + nt * 8 + g;
                bh[nt][0] = base[OFF_BH + r0 * BSTR + cn];
                bh[nt][1] = base[OFF_BH + r1 * BSTR + cn];
                bl[nt][0] = base[OFF_BL + r0 * BSTR + cn];
                bl[nt][1] = base[OFF_BL + r1 * BSTR + cn];
            }
#pragma unroll
            for (int mt = 0; mt < 4; mt++)
#pragma unroll
                for (int nt = 0; nt < 4; nt++) {
                    mma_tf32(acc[mt][nt], ah[mt][0], ah[mt][1], ah[mt][2], ah[mt][3],
                             bh[nt][0], bh[nt][1]);
                    mma_tf32(acc[mt][nt], ah[mt][0], ah[mt][1], ah[mt][2], ah[mt][3],
                             bl[nt][0], bl[nt][1]);
                    mma_tf32(acc[mt][nt], al[mt][0], al[mt][1], al[mt][2], al[mt][3],
                             bh[nt][0], bh[nt][1]);
                }
        }
    };

    gload(0);
    sstore(0);
    __syncthreads();

    for (int kt = 0; kt < 64; kt++) {
        if (kt < 63) gload((kt + 1) * 16);
        compute(kt & 1);
        if (kt < 63) sstore((kt + 1) & 1);
        __syncthreads();
    }

    // epilogue: c frag -> g_h (float2 per pair of columns)
#pragma unroll
    for (int mt = 0; mt < 4; mt++)
#pragma unroll
        for (int nt = 0; nt < 4; nt++) {
            const int row0 = bm + wm + mt * 16 + g;
            const int col  = bn + wn + nt * 8 + t4 * 2;
            *(float2*)&g_h[(size_t)row0 * O_ + col] =
                make_float2(acc[mt][nt][0], acc[mt][nt][1]);
            *(float2*)&g_h[(size_t)(row0 + 8) * O_ + col] =
                make_float2(acc[mt][nt][2], acc[mt][nt][3]);
        }
}

// ---------------------------------------------------------------------------
// GEMM 2 (SIMT): g_d[i,o] = sum_a w[a,i]*w[a,o]  (A^T A, A = w [1024,1024])
// ---------------------------------------------------------------------------
__global__ __launch_bounds__(256, 2) void gemm_d(const float* __restrict__ W)
{
    __shared__ float As[8][128];
    __shared__ float Bs[8][132];

    const int tid = threadIdx.x;
    const int bm = blockIdx.y * 128;
    const int bn = blockIdx.x * 128;
    const int K = I_, N = O_;

    const int brow = tid >> 5;
    const int bcol = (tid & 31) * 4;
    const int tr   = (tid >> 4) * 8;
    const int tc   = (tid & 15) * 8;

    float acc[8][8];
#pragma unroll
    for (int i = 0; i < 8; i++)
#pragma unroll
        for (int j = 0; j < 8; j++) acc[i][j] = 0.f;

    for (int k0 = 0; k0 < K; k0 += 8) {
        float4 a4 = *(const float4*)&W[(size_t)(k0 + brow) * N + bm + bcol];
        float4 b4 = *(const float4*)&W[(size_t)(k0 + brow) * N + bn + bcol];
        __syncthreads();
        *(float4*)&As[brow][bcol & 127] = a4;
        *(float4*)&Bs[brow][bcol] = b4;
        __syncthreads();
#pragma unroll
        for (int kk = 0; kk < 8; kk++) {
            float ar[8], br[8];
#pragma unroll
            for (int i = 0; i < 8; i++) ar[i] = As[kk][tr + i];
#pragma unroll
            for (int j = 0; j < 8; j++) br[j] = Bs[kk][tc + j];
#pragma unroll
            for (int i = 0; i < 8; i++)
#pragma unroll
                for (int j = 0; j < 8; j++) acc[i][j] += ar[i] * br[j];
        }
    }

#pragma unroll
    for (int i = 0; i < 8; i++)
#pragma unroll
        for (int j = 0; j < 8; j += 4) {
            float4 o4 = make_float4(acc[i][j], acc[i][j + 1], acc[i][j + 2], acc[i][j + 3]);
            *(float4*)&g_d[(size_t)(bm + tr + i) * N + bn + tc + j] = o4;
        }
}

// ---------------------------------------------------------------------------
// prep: inv_norm from diag(d), zero per-step counters
// ---------------------------------------------------------------------------
__global__ void prep_kernel()
{
    int idx = blockIdx.x * blockDim.x + threadIdx.x;
    if (idx < O_) g_inv[idx] = 1.0f / (g_d[(size_t)idx * O_ + idx] + EPSV);
    if (idx < T_) g_cnt[idx] = 0;
}

// ---------------------------------------------------------------------------
// Scan v2: one CTA per batch, 1024 threads, one neuron per thread.
// mem in a register; spike list double-buffered; h prefetched one step ahead.
// Sparse-exact: rst/rec sum only active rows of d / V (adding 0.0 is exact).
// ---------------------------------------------------------------------------
__global__ void __launch_bounds__(1024) scan_kernel(
    const float* __restrict__ V,
    const float* __restrict__ bb,
    const float* __restrict__ beta_p,
    float* __restrict__ out)
{
    const int b = blockIdx.x;
    const int o = threadIdx.x;          // neuron index, 0..1023
    const float beta = beta_p[0];
    const float ombeta = 1.0f - beta;

    __shared__ int act[2][O_];
    __shared__ int nact[2];
    __shared__ int scnt;

    if (o < 2) nact[o] = 0;
    if (o == 0) scnt = 0;

    float mem = 0.f;
    const float inv = g_inv[o];
    const float bo  = bb[o];
    const float* hrow = g_h + (size_t)b * T_ * O_ + o;
    float*       orow = out + (size_t)b * T_ * O_ + o;

    float h_next = hrow[0];
    __syncthreads();

    int cur = 0;
    for (int t = 0; t < T_; t++) {
        const float h_cur = h_next;
        if (t + 1 < T_) h_next = hrow[(size_t)(t + 1) * O_];   // prefetch

        const int na = nact[cur];
        float rst = 0.f, rec = 0.f;
        for (int a = 0; a < na; a++) {
            const int i = act[cur][a];
            rst += g_d[(size_t)i * O_ + o];
            rec += V[(size_t)i * O_ + o];
        }

        mem = (mem - rst) * beta + (h_cur + rec) * ombeta;
        const float mthr = mem * inv - bo;
        const float s = (mthr > 0.f) ? 1.0f : 0.0f;
        orow[(size_t)t * O_] = s;
        if (s != 0.f) {
            const int p = atomicAdd(&nact[cur ^ 1], 1);
            act[cur ^ 1][p] = o;
            atomicAdd(&scnt, 1);
        }
        __syncthreads();
        if (o == 0) {
            if (scnt) { atomicAdd(&g_cnt[t], scnt); scnt = 0; }
            nact[cur] = 0;
        }
        cur ^= 1;
        __syncthreads();
    }
}

// ---------------------------------------------------------------------------
// finalize: loss and spike-spread scalars
// ---------------------------------------------------------------------------
__global__ void finalize_kernel(float* __restrict__ out, int out_size)
{
    __shared__ int s_tot[128];
    __shared__ int s_max[128];
    const int tid = threadIdx.x;
    int tot = 0, mx = 0;
    for (int t = tid; t < T_; t += 128) {
        int c = g_cnt[t];
        tot += c;
        mx = (c > mx) ? c : mx;
    }
    s_tot[tid] = tot; s_max[tid] = mx;
    __syncthreads();
    for (int s = 64; s > 0; s >>= 1) {
        if (tid < s) {
            s_tot[tid] += s_tot[tid + s];
            s_max[tid] = (s_max[tid + s] > s_max[tid]) ? s_max[tid + s] : s_max[tid];
        }
        __syncthreads();
    }
    if (tid == 0) {
        const size_t base = (size_t)B_ * T_ * O_;
        if ((size_t)out_size >= base + 2) {
            out[base]     = 0.5f * (float)s_tot[0] / (float)((size_t)B_ * T_ * O_);
            out[base + 1] = (float)s_max[0] / (float)(B_ * O_);
        }
    }
}

// ---------------------------------------------------------------------------
extern "C" void kernel_launch(void* const* d_in, const int* in_sizes, int n_in,
                              void* d_out, int out_size)
{
    const float* x    = (const float*)d_in[0];   // [B,T,I]
    const float* w    = (const float*)d_in[1];   // [I,O]
    const float* v    = (const float*)d_in[2];   // [O,O]
    const float* beta = (const float*)d_in[3];   // [1]
    const float* bb   = (const float*)d_in[4];   // [O]
    float* out = (float*)d_out;

    cudaFuncSetAttribute(gemm_h_mma, cudaFuncAttributeMaxDynamicSharedMemorySize,
                         GH_SMEM_BYTES);

    // 1) h = x @ w via mma.sync tf32 (3xTF32)
    gemm_h_mma<<<dim3(O_ / 128, (B_ * T_) / 128), 256, GH_SMEM_BYTES>>>(x, w);

    // 2) d = w^T w (SIMT)
    gemm_d<<<dim3(O_ / 128, O_ / 128), 256>>>(w);

    // 3) inv_norm + zero counters
    prep_kernel<<<4, 256>>>();

    // 4) per-batch recurrent scan
    scan_kernel<<<B_, 1024>>>(v, bb, beta, out);

    // 5) scalar losses
    finalize_kernel<<<1, 128>>>(out, out_size);
}